// round 13
// baseline (speedup 1.0000x reference)
#include <cuda_runtime.h>
#include <math.h>
#include <stdint.h>

// Problem constants
#define Bn   8
#define CIN  128
#define Hn   64
#define Wn   64
#define HWn  4096          // 64*64
#define COUT_MAIN 128

typedef unsigned long long ull;

// ---------------- device scratch (no allocations allowed) ----------------
__device__ float g_xnhwc[Bn * HWn * CIN];        // x transposed to NHWC (16 MB)
__device__ float g_offmask[Bn * HWn * 27];       // per-pixel: dy0,dx0,...,dy8,dx8, m0..m8
__device__ float g_wt_main[9 * CIN * COUT_MAIN]; // [k][c][co]
__device__ float g_wt_om[9 * CIN * 32];          // [k][c][o] (27 padded to 32)

// ---------------- f32x2 / async helpers ----------------
__device__ __forceinline__ ull dup2(float x) {
    ull r;
    asm("mov.b64 %0, {%1, %1};" : "=l"(r) : "r"(__float_as_uint(x)));
    return r;
}
__device__ __forceinline__ ull ffma2(ull a, ull b, ull c) {
    ull d;
    asm("fma.rn.f32x2 %0, %1, %2, %3;" : "=l"(d) : "l"(a), "l"(b), "l"(c));
    return d;
}
__device__ __forceinline__ float f2lo(ull v) { return __uint_as_float((unsigned)v); }
__device__ __forceinline__ float f2hi(ull v) { return __uint_as_float((unsigned)(v >> 32)); }

__device__ __forceinline__ void cp16(uint32_t smem_dst, const void* gsrc) {
    asm volatile("cp.async.cg.shared.global [%0], [%1], 16;" :: "r"(smem_dst), "l"(gsrc));
}
__device__ __forceinline__ void cp_commit() {
    asm volatile("cp.async.commit_group;" ::: "memory");
}
__device__ __forceinline__ void cp_wait_all() {
    asm volatile("cp.async.wait_group 0;" ::: "memory");
}

// ---------------- kernel 0: NCHW -> NHWC transpose ----------------
__global__ void k_transpose(const float* __restrict__ x) {
    __shared__ float s[128][65];
    int bh = blockIdx.x;
    int b = bh >> 6, h = bh & 63;
    int t = threadIdx.x;
    const float* xp = x + (size_t)b * (CIN * HWn) + h * 64;
    for (int idx = t; idx < 8192; idx += 256) {
        int c = idx >> 6, w = idx & 63;
        s[c][w] = xp[c * HWn + w];
    }
    __syncthreads();
    float* op = g_xnhwc + (size_t)((b << 6) | h) * 64 * CIN;
    for (int idx = t; idx < 8192; idx += 256) {
        int w = idx >> 7, c = idx & 127;
        op[w * CIN + c] = s[c][w];
    }
}

// ---------------- kernel 1: weight re-layout ----------------
__global__ void k_prep(const float* __restrict__ w_reg,
                       const float* __restrict__ w_off,
                       const float* __restrict__ w_mod) {
    int i = blockIdx.x * 256 + threadIdx.x;
    if (i < 9 * 128 * 128) {
        int co = i & 127, c = (i >> 7) & 127, k = i >> 14;
        g_wt_main[(k * 128 + c) * 128 + co] = w_reg[co * 1152 + c * 9 + k];
    }
    int j = i - 9 * 128 * 128;
    if (j >= 0 && j < 9 * 128 * 32) {
        int o = j & 31, c = (j >> 5) & 127, k = j >> 12;
        float v = 0.f;
        if (o < 18)      v = w_off[o * 1152 + c * 9 + k];
        else if (o < 27) v = w_mod[(o - 18) * 1152 + c * 9 + k];
        g_wt_om[(k * 128 + c) * 32 + o] = v;
    }
}

// corner gather: accumulate wgt * x[yi, xi, ch] into vr (32 channels per thread)
__device__ __forceinline__ void corner_acc(float4* vr, const float* xb, int gl,
                                           int yi, int xi, float wgt) {
    if (wgt != 0.f && (unsigned)yi < 64u && (unsigned)xi < 64u) {
        const float4* s4 = reinterpret_cast<const float4*>(xb + (size_t)((yi << 6) + xi) * CIN) + gl;
#pragma unroll
        for (int i = 0; i < 8; ++i) {
            float4 xv = __ldg(s4 + (i << 2));
            vr[i].x = fmaf(wgt, xv.x, vr[i].x);
            vr[i].y = fmaf(wgt, xv.y, vr[i].y);
            vr[i].z = fmaf(wgt, xv.z, vr[i].z);
            vr[i].w = fmaf(wgt, xv.w, vr[i].w);
        }
    }
}

// store vr (32 channels for pixel gp) into a Vs buffer with swizzle
__device__ __forceinline__ void sts_vr(float* vbuf, const float4* vr, int gp, int gl) {
    int px = gp ^ (gl << 3);        // swizzle: ((c0>>2)&3)<<3 == gl<<3
#pragma unroll
    for (int i = 0; i < 8; ++i) {
        int c0 = (gl + (i << 2)) << 2;
        vbuf[(c0 + 0) * 64 + px] = vr[i].x;
        vbuf[(c0 + 1) * 64 + px] = vr[i].y;
        vbuf[(c0 + 2) * 64 + px] = vr[i].z;
        vbuf[(c0 + 3) * 64 + px] = vr[i].w;
    }
}

// ---------------- main kernel: deformable conv block-GEMM (pipelined) ----------------
// Block = one (b, ho) output row: 64 px x 128 out, K = 9 taps * 128 ch.
// Vs double-buffered; Phase A for tap k+1 distributed over Phase B chunks of tap k.
// Ws double-buffered via cp.async, 32-channel chunks.
__global__ __launch_bounds__(256, 2)
void k_main(float* __restrict__ out) {
    extern __shared__ float sm[];
    float* Vs  = sm;                 // [2][128*64]  = 16384 floats
    float* Wsm = sm + 16384;         // [2][32*128]  =  8192 floats
    float* OM  = sm + 24576;         // [64*27]      =  1728 floats

    const int bh = blockIdx.x;
    const int b  = bh >> 6;
    const int ho = bh & 63;
    const int t  = threadIdx.x;
    const int tx = t & 15;           // pixel group (4 px)
    const int ty = t >> 4;           // output group (8 outs = 4 pairs)
    const int gp = t >> 2;           // gather pixel
    const int gl = t & 3;            // gather lane (32 channels)

    const uint32_t ws_sm = (uint32_t)__cvta_generic_to_shared(Wsm);

    ull acc[4][4];
#pragma unroll
    for (int j = 0; j < 4; ++j)
#pragma unroll
        for (int i = 0; i < 4; ++i) acc[j][i] = 0ULL;

    // load offsets/masks for this row
    {
        const float* src = g_offmask + (size_t)bh * 64 * 27;
        for (int i = t; i < 64 * 27; i += 256) OM[i] = src[i];
    }
    // prefetch Ws chunk g=0 (tap0, channels 0..31)
    {
        uint32_t d = ws_sm + t * 64;
        const char* s = (const char*)g_wt_main + t * 64;
        cp16(d, s); cp16(d + 16, s + 16); cp16(d + 32, s + 32); cp16(d + 48, s + 48);
        cp_commit();
    }
    __syncthreads();  // OM visible

    const float* xb = g_xnhwc + (size_t)b * HWn * CIN;
    const float* omp = &OM[gp * 27];

    // prologue: Phase A for tap 0 -> Vs[0]
    {
        float dy = omp[0], dx = omp[1], m = omp[18];
        float py = (float)(ho - 1) + dy;
        float px = (float)(gp - 1) + dx;
        float y0f = floorf(py), x0f = floorf(px);
        float wy = py - y0f, wx = px - x0f;
        int y0 = (int)y0f, x0 = (int)x0f;
        float4 vr[8];
#pragma unroll
        for (int i = 0; i < 8; ++i) vr[i] = make_float4(0.f, 0.f, 0.f, 0.f);
        corner_acc(vr, xb, gl, y0,     x0,     (1.f - wy) * (1.f - wx) * m);
        corner_acc(vr, xb, gl, y0,     x0 + 1, (1.f - wy) * wx * m);
        corner_acc(vr, xb, gl, y0 + 1, x0,     wy * (1.f - wx) * m);
        corner_acc(vr, xb, gl, y0 + 1, x0 + 1, wy * wx * m);
        sts_vr(Vs, vr, gp, gl);
    }

    float4 vr[8];
    int ny0 = 0, nx0 = 0;
    float nw01 = 0.f, nw10 = 0.f, nw11 = 0.f;

#pragma unroll 1
    for (int k = 0; k < 9; ++k) {
        const float* vcur  = Vs + (k & 1) * 8192;
        float*       vnext = Vs + ((k + 1) & 1) * 8192;

#pragma unroll 1
        for (int cc = 0; cc < 4; ++cc) {
            const int g = k * 4 + cc;
            cp_wait_all();           // my cp.async for chunk g done
            __syncthreads();         // everyone's done; buf (g+1)&1 free; Vs writes visible

            // prefetch next weight chunk into the other buffer
            if (g + 1 < 36) {
                uint32_t d = ws_sm + ((g + 1) & 1) * 16384 + t * 64;
                const char* s = (const char*)g_wt_main + (size_t)(g + 1) * 16384 + t * 64;
                cp16(d, s); cp16(d + 16, s + 16); cp16(d + 32, s + 32); cp16(d + 48, s + 48);
                cp_commit();
            }

            // Phase A for tap k+1: one bilinear corner per chunk
            if (k < 8) {
                const int kn = k + 1;
                if (cc == 0) {
#pragma unroll
                    for (int i = 0; i < 8; ++i) vr[i] = make_float4(0.f, 0.f, 0.f, 0.f);
                    float dy = omp[2 * kn], dx = omp[2 * kn + 1], m = omp[18 + kn];
                    float py = (float)(ho + kn / 3 - 1) + dy;
                    float px = (float)(gp + kn % 3 - 1) + dx;
                    float y0f = floorf(py), x0f = floorf(px);
                    float wy = py - y0f, wx = px - x0f;
                    ny0 = (int)y0f; nx0 = (int)x0f;
                    nw01 = (1.f - wy) * wx * m;
                    nw10 = wy * (1.f - wx) * m;
                    nw11 = wy * wx * m;
                    corner_acc(vr, xb, gl, ny0, nx0, (1.f - wy) * (1.f - wx) * m);
                } else if (cc == 1) {
                    corner_acc(vr, xb, gl, ny0, nx0 + 1, nw01);
                } else if (cc == 2) {
                    corner_acc(vr, xb, gl, ny0 + 1, nx0, nw10);
                } else {
                    corner_acc(vr, xb, gl, ny0 + 1, nx0 + 1, nw11);
                    sts_vr(vnext, vr, gp, gl);
                }
            }

            // GEMM on this 32-channel chunk
            const float* wsb = Wsm + (g & 1) * 4096 + ty * 8;
            const float* vcb = vcur + (cc << 5) * 64;
#pragma unroll 8
            for (int c = 0; c < 32; ++c) {
                int sw = ((c >> 2) & 3) << 3;
                float4 v4 = *reinterpret_cast<const float4*>(vcb + c * 64 + ((tx << 2) ^ sw));
                ull d0 = dup2(v4.x), d1 = dup2(v4.y), d2 = dup2(v4.z), d3 = dup2(v4.w);
                const ull* wp = reinterpret_cast<const ull*>(wsb + c * 128);
#pragma unroll
                for (int j = 0; j < 4; ++j) {
                    ull w = wp[j];
                    acc[j][0] = ffma2(w, d0, acc[j][0]);
                    acc[j][1] = ffma2(w, d1, acc[j][1]);
                    acc[j][2] = ffma2(w, d2, acc[j][2]);
                    acc[j][3] = ffma2(w, d3, acc[j][3]);
                }
            }
        }
    }

    // epilogue -> NCHW
    float* ob = out + (size_t)b * COUT_MAIN * HWn + (ho << 6) + (tx << 2);
#pragma unroll
    for (int j = 0; j < 4; ++j) {
        int co0 = ty * 8 + 2 * j;
        float4 r0, r1;
        r0.x = f2lo(acc[j][0]); r0.y = f2lo(acc[j][1]);
        r0.z = f2lo(acc[j][2]); r0.w = f2lo(acc[j][3]);
        r1.x = f2hi(acc[j][0]); r1.y = f2hi(acc[j][1]);
        r1.z = f2hi(acc[j][2]); r1.w = f2hi(acc[j][3]);
        *reinterpret_cast<float4*>(ob + (size_t)co0 * HWn)       = r0;
        *reinterpret_cast<float4*>(ob + (size_t)(co0 + 1) * HWn) = r1;
    }
}

// ---------------- aux kernel: plain 3x3 conv producing offsets+masks ----------------
// Block = 2 output rows (128 px) x 32 outputs (27 used). Integer taps (pure copy
// Phase A). Ws double-buffered via cp.async.
__global__ __launch_bounds__(256, 2)
void k_aux(const float* __restrict__ b_off, const float* __restrict__ b_mod) {
    extern __shared__ float sm[];
    float* Vs  = sm;               // [128ch][128px] = 16384 floats
    float* Wsm = sm + 16384;       // [2][32*32]     =  2048 floats

    const int blk = blockIdx.x;
    const int b   = blk >> 5;
    const int ho0 = (blk & 31) << 1;
    const int t   = threadIdx.x;
    const int tx  = t & 31;        // pixel group (4 px of 128)
    const int ty  = t >> 5;        // output group (4 outs = 2 pairs)
    const int tp  = t >> 1;        // copy pixel 0..127
    const int th  = t & 1;         // copy half (64 channels)

    const uint32_t ws_sm = (uint32_t)__cvta_generic_to_shared(Wsm);

    ull acc[2][4];
#pragma unroll
    for (int j = 0; j < 2; ++j)
#pragma unroll
        for (int i = 0; i < 4; ++i) acc[j][i] = 0ULL;

    // prefetch chunk 0
    cp16(ws_sm + t * 16, (const char*)g_wt_om + t * 16);
    cp_commit();

    const float* xb = g_xnhwc + (size_t)b * HWn * CIN;

#pragma unroll 1
    for (int k = 0; k < 9; ++k) {
        const int kh = k / 3, kw = k % 3;
        __syncthreads();  // all done reading Vs from previous tap

        // Phase A: guarded row copy (integer taps)
        {
            int row = tp >> 6, col = tp & 63;
            int ys = ho0 + row + kh - 1;
            int xs = col + kw - 1;
            bool val = ((unsigned)ys < 64u) && ((unsigned)xs < 64u);
            size_t base = val ? (size_t)((ys << 6) + xs) * CIN : 0;
            const float4* s4 = reinterpret_cast<const float4*>(xb + base) + th * 16;
#pragma unroll
            for (int j = 0; j < 16; ++j) {
                float4 xv = val ? __ldg(s4 + j) : make_float4(0.f, 0.f, 0.f, 0.f);
                int c0 = (th << 6) + (j << 2);
                Vs[(c0 + 0) * 128 + tp] = xv.x;
                Vs[(c0 + 1) * 128 + tp] = xv.y;
                Vs[(c0 + 2) * 128 + tp] = xv.z;
                Vs[(c0 + 3) * 128 + tp] = xv.w;
            }
        }

#pragma unroll 1
        for (int cc = 0; cc < 4; ++cc) {
            const int g = k * 4 + cc;
            cp_wait_all();
            __syncthreads();  // Ws chunk ready; Phase A STS visible (cc==0); other buf free

            if (g + 1 < 36) {
                cp16(ws_sm + ((g + 1) & 1) * 4096 + t * 16,
                     (const char*)g_wt_om + (size_t)(g + 1) * 4096 + t * 16);
                cp_commit();
            }

            const float* wsb = Wsm + (g & 1) * 1024 + (ty << 2);
            const float* vcb = Vs + (cc << 5) * 128 + (tx << 2);
#pragma unroll 8
            for (int c = 0; c < 32; ++c) {
                float4 v4 = *reinterpret_cast<const float4*>(vcb + c * 128);
                ull d0 = dup2(v4.x), d1 = dup2(v4.y), d2 = dup2(v4.z), d3 = dup2(v4.w);
                const ull* wp = reinterpret_cast<const ull*>(wsb + c * 32);
#pragma unroll
                for (int j = 0; j < 2; ++j) {
                    ull w = wp[j];
                    acc[j][0] = ffma2(w, d0, acc[j][0]);
                    acc[j][1] = ffma2(w, d1, acc[j][1]);
                    acc[j][2] = ffma2(w, d2, acc[j][2]);
                    acc[j][3] = ffma2(w, d3, acc[j][3]);
                }
            }
        }
    }

    // epilogue: bias (+ 2*sigmoid for mask channels) -> g_offmask
#pragma unroll
    for (int j = 0; j < 2; ++j) {
#pragma unroll
        for (int h = 0; h < 2; ++h) {
            int o = (ty << 2) + (j << 1) + h;
            if (o < 27) {
                float bias = (o < 18) ? b_off[o] : b_mod[o - 18];
#pragma unroll
                for (int i = 0; i < 4; ++i) {
                    int p = (tx << 2) + i;
                    int row = ho0 + (p >> 6), col = p & 63;
                    float v = (h ? f2hi(acc[j][i]) : f2lo(acc[j][i])) + bias;
                    if (o >= 18) v = 2.f / (1.f + expf(-v));
                    g_offmask[(size_t)(((b << 6) + row) * 64 + col) * 27 + o] = v;
                }
            }
        }
    }
}

// ---------------- launch ----------------
extern "C" void kernel_launch(void* const* d_in, const int* in_sizes, int n_in,
                              void* d_out, int out_size) {
    const float* x     = (const float*)d_in[0];
    const float* w_off = (const float*)d_in[1];
    const float* b_off = (const float*)d_in[2];
    const float* w_mod = (const float*)d_in[3];
    const float* b_mod = (const float*)d_in[4];
    const float* w_reg = (const float*)d_in[5];
    float* out = (float*)d_out;

    const int SMEM_MAIN = (16384 + 8192 + 1728) * 4;   // 105216 B
    const int SMEM_AUX  = (16384 + 2048) * 4;          //  73728 B
    cudaFuncSetAttribute(k_main, cudaFuncAttributeMaxDynamicSharedMemorySize, SMEM_MAIN);
    cudaFuncSetAttribute(k_aux,  cudaFuncAttributeMaxDynamicSharedMemorySize, SMEM_AUX);

    k_transpose<<<Bn * Hn, 256>>>(x);
    k_prep<<<(9 * 128 * 128 + 9 * 128 * 32 + 255) / 256, 256>>>(w_reg, w_off, w_mod);
    k_aux<<<Bn * 32, 256, SMEM_AUX>>>(b_off, b_mod);
    k_main<<<Bn * Hn, 256, SMEM_MAIN>>>(out);
}

// round 14
// speedup vs baseline: 1.0016x; 1.0016x over previous
#include <cuda_runtime.h>
#include <math.h>
#include <stdint.h>

// Problem constants
#define Bn   8
#define CIN  128
#define Hn   64
#define Wn   64
#define HWn  4096          // 64*64
#define COUT_MAIN 128

typedef unsigned long long ull;

// ---------------- device scratch (no allocations allowed) ----------------
__device__ float g_xnhwc[Bn * HWn * CIN];        // x transposed to NHWC (16 MB)
__device__ float g_offmask[Bn * HWn * 27];       // per-pixel: dy0,dx0,...,dy8,dx8, m0..m8
__device__ float g_wt_main[9 * CIN * COUT_MAIN]; // [k][c][co]
__device__ float g_wt_om[9 * CIN * 32];          // [k][c][o] (27 padded to 32)

// ---------------- f32x2 / async helpers ----------------
__device__ __forceinline__ ull dup2(float x) {
    ull r;
    asm("mov.b64 %0, {%1, %1};" : "=l"(r) : "r"(__float_as_uint(x)));
    return r;
}
__device__ __forceinline__ ull ffma2(ull a, ull b, ull c) {
    ull d;
    asm("fma.rn.f32x2 %0, %1, %2, %3;" : "=l"(d) : "l"(a), "l"(b), "l"(c));
    return d;
}
__device__ __forceinline__ float f2lo(ull v) { return __uint_as_float((unsigned)v); }
__device__ __forceinline__ float f2hi(ull v) { return __uint_as_float((unsigned)(v >> 32)); }

__device__ __forceinline__ void cp16(uint32_t smem_dst, const void* gsrc) {
    asm volatile("cp.async.cg.shared.global [%0], [%1], 16;" :: "r"(smem_dst), "l"(gsrc));
}
__device__ __forceinline__ void cp_commit() {
    asm volatile("cp.async.commit_group;" ::: "memory");
}
__device__ __forceinline__ void cp_wait_all() {
    asm volatile("cp.async.wait_group 0;" ::: "memory");
}

// ---------------- kernel 0: NCHW -> NHWC transpose ----------------
__global__ void k_transpose(const float* __restrict__ x) {
    __shared__ float s[128][65];
    int bh = blockIdx.x;
    int b = bh >> 6, h = bh & 63;
    int t = threadIdx.x;
    const float* xp = x + (size_t)b * (CIN * HWn) + h * 64;
    for (int idx = t; idx < 8192; idx += 256) {
        int c = idx >> 6, w = idx & 63;
        s[c][w] = xp[c * HWn + w];
    }
    __syncthreads();
    float* op = g_xnhwc + (size_t)((b << 6) | h) * 64 * CIN;
    for (int idx = t; idx < 8192; idx += 256) {
        int w = idx >> 7, c = idx & 127;
        op[w * CIN + c] = s[c][w];
    }
}

// ---------------- kernel 1: weight re-layout ----------------
__global__ void k_prep(const float* __restrict__ w_reg,
                       const float* __restrict__ w_off,
                       const float* __restrict__ w_mod) {
    int i = blockIdx.x * 256 + threadIdx.x;
    if (i < 9 * 128 * 128) {
        int co = i & 127, c = (i >> 7) & 127, k = i >> 14;
        g_wt_main[(k * 128 + c) * 128 + co] = w_reg[co * 1152 + c * 9 + k];
    }
    int j = i - 9 * 128 * 128;
    if (j >= 0 && j < 9 * 128 * 32) {
        int o = j & 31, c = (j >> 5) & 127, k = j >> 12;
        float v = 0.f;
        if (o < 18)      v = w_off[o * 1152 + c * 9 + k];
        else if (o < 27) v = w_mod[(o - 18) * 1152 + c * 9 + k];
        g_wt_om[(k * 128 + c) * 32 + o] = v;
    }
}

// corner gather: accumulate wgt * x[yi, xi, ch] into vr (32 channels per thread)
__device__ __forceinline__ void corner_acc(float4* vr, const float* xb, int gl,
                                           int yi, int xi, float wgt) {
    if (wgt != 0.f && (unsigned)yi < 64u && (unsigned)xi < 64u) {
        const float4* s4 = reinterpret_cast<const float4*>(xb + (size_t)((yi << 6) + xi) * CIN) + gl;
#pragma unroll
        for (int i = 0; i < 8; ++i) {
            float4 xv = __ldg(s4 + (i << 2));
            vr[i].x = fmaf(wgt, xv.x, vr[i].x);
            vr[i].y = fmaf(wgt, xv.y, vr[i].y);
            vr[i].z = fmaf(wgt, xv.z, vr[i].z);
            vr[i].w = fmaf(wgt, xv.w, vr[i].w);
        }
    }
}

// store vr (32 channels for pixel gp) into a Vs buffer with swizzle
__device__ __forceinline__ void sts_vr(float* vbuf, const float4* vr, int gp, int gl) {
    int px = gp ^ (gl << 3);        // swizzle: ((c0>>2)&3)<<3 == gl<<3
#pragma unroll
    for (int i = 0; i < 8; ++i) {
        int c0 = (gl + (i << 2)) << 2;
        vbuf[(c0 + 0) * 64 + px] = vr[i].x;
        vbuf[(c0 + 1) * 64 + px] = vr[i].y;
        vbuf[(c0 + 2) * 64 + px] = vr[i].z;
        vbuf[(c0 + 3) * 64 + px] = vr[i].w;
    }
}

// ---------------- main kernel: deformable conv block-GEMM (pipelined) ----------------
// Block = one (b, ho) output row: 64 px x 128 out, K = 9 taps * 128 ch.
// Vs double-buffered; Phase A for tap k+1 distributed over Phase B chunks of tap k.
// Ws double-buffered via cp.async, 32-channel chunks.
__global__ __launch_bounds__(256, 2)
void k_main(float* __restrict__ out) {
    extern __shared__ float sm[];
    float* Vs  = sm;                 // [2][128*64]  = 16384 floats
    float* Wsm = sm + 16384;         // [2][32*128]  =  8192 floats
    float* OM  = sm + 24576;         // [64*27]      =  1728 floats

    const int bh = blockIdx.x;
    const int b  = bh >> 6;
    const int ho = bh & 63;
    const int t  = threadIdx.x;
    const int tx = t & 15;           // pixel group (4 px)
    const int ty = t >> 4;           // output group (8 outs = 4 pairs)
    const int gp = t >> 2;           // gather pixel
    const int gl = t & 3;            // gather lane (32 channels)

    const uint32_t ws_sm = (uint32_t)__cvta_generic_to_shared(Wsm);

    ull acc[4][4];
#pragma unroll
    for (int j = 0; j < 4; ++j)
#pragma unroll
        for (int i = 0; i < 4; ++i) acc[j][i] = 0ULL;

    // load offsets/masks for this row
    {
        const float* src = g_offmask + (size_t)bh * 64 * 27;
        for (int i = t; i < 64 * 27; i += 256) OM[i] = src[i];
    }
    // prefetch Ws chunk g=0 (tap0, channels 0..31)
    {
        uint32_t d = ws_sm + t * 64;
        const char* s = (const char*)g_wt_main + t * 64;
        cp16(d, s); cp16(d + 16, s + 16); cp16(d + 32, s + 32); cp16(d + 48, s + 48);
        cp_commit();
    }
    __syncthreads();  // OM visible

    const float* xb = g_xnhwc + (size_t)b * HWn * CIN;
    const float* omp = &OM[gp * 27];

    // prologue: Phase A for tap 0 -> Vs[0]
    {
        float dy = omp[0], dx = omp[1], m = omp[18];
        float py = (float)(ho - 1) + dy;
        float px = (float)(gp - 1) + dx;
        float y0f = floorf(py), x0f = floorf(px);
        float wy = py - y0f, wx = px - x0f;
        int y0 = (int)y0f, x0 = (int)x0f;
        float4 vr[8];
#pragma unroll
        for (int i = 0; i < 8; ++i) vr[i] = make_float4(0.f, 0.f, 0.f, 0.f);
        corner_acc(vr, xb, gl, y0,     x0,     (1.f - wy) * (1.f - wx) * m);
        corner_acc(vr, xb, gl, y0,     x0 + 1, (1.f - wy) * wx * m);
        corner_acc(vr, xb, gl, y0 + 1, x0,     wy * (1.f - wx) * m);
        corner_acc(vr, xb, gl, y0 + 1, x0 + 1, wy * wx * m);
        sts_vr(Vs, vr, gp, gl);
    }

    float4 vr[8];
    int ny0 = 0, nx0 = 0;
    float nw01 = 0.f, nw10 = 0.f, nw11 = 0.f;

#pragma unroll 1
    for (int k = 0; k < 9; ++k) {
        const float* vcur  = Vs + (k & 1) * 8192;
        float*       vnext = Vs + ((k + 1) & 1) * 8192;

#pragma unroll 1
        for (int cc = 0; cc < 4; ++cc) {
            const int g = k * 4 + cc;
            cp_wait_all();           // my cp.async for chunk g done
            __syncthreads();         // everyone's done; buf (g+1)&1 free; Vs writes visible

            // prefetch next weight chunk into the other buffer
            if (g + 1 < 36) {
                uint32_t d = ws_sm + ((g + 1) & 1) * 16384 + t * 64;
                const char* s = (const char*)g_wt_main + (size_t)(g + 1) * 16384 + t * 64;
                cp16(d, s); cp16(d + 16, s + 16); cp16(d + 32, s + 32); cp16(d + 48, s + 48);
                cp_commit();
            }

            // Phase A for tap k+1: one bilinear corner per chunk
            if (k < 8) {
                const int kn = k + 1;
                if (cc == 0) {
#pragma unroll
                    for (int i = 0; i < 8; ++i) vr[i] = make_float4(0.f, 0.f, 0.f, 0.f);
                    float dy = omp[2 * kn], dx = omp[2 * kn + 1], m = omp[18 + kn];
                    float py = (float)(ho + kn / 3 - 1) + dy;
                    float px = (float)(gp + kn % 3 - 1) + dx;
                    float y0f = floorf(py), x0f = floorf(px);
                    float wy = py - y0f, wx = px - x0f;
                    ny0 = (int)y0f; nx0 = (int)x0f;
                    nw01 = (1.f - wy) * wx * m;
                    nw10 = wy * (1.f - wx) * m;
                    nw11 = wy * wx * m;
                    corner_acc(vr, xb, gl, ny0, nx0, (1.f - wy) * (1.f - wx) * m);
                } else if (cc == 1) {
                    corner_acc(vr, xb, gl, ny0, nx0 + 1, nw01);
                } else if (cc == 2) {
                    corner_acc(vr, xb, gl, ny0 + 1, nx0, nw10);
                } else {
                    corner_acc(vr, xb, gl, ny0 + 1, nx0 + 1, nw11);
                    sts_vr(vnext, vr, gp, gl);
                }
            }

            // GEMM on this 32-channel chunk
            const float* wsb = Wsm + (g & 1) * 4096 + ty * 8;
            const float* vcb = vcur + (cc << 5) * 64;
#pragma unroll 8
            for (int c = 0; c < 32; ++c) {
                int sw = ((c >> 2) & 3) << 3;
                float4 v4 = *reinterpret_cast<const float4*>(vcb + c * 64 + ((tx << 2) ^ sw));
                ull d0 = dup2(v4.x), d1 = dup2(v4.y), d2 = dup2(v4.z), d3 = dup2(v4.w);
                const ull* wp = reinterpret_cast<const ull*>(wsb + c * 128);
#pragma unroll
                for (int j = 0; j < 4; ++j) {
                    ull w = wp[j];
                    acc[j][0] = ffma2(w, d0, acc[j][0]);
                    acc[j][1] = ffma2(w, d1, acc[j][1]);
                    acc[j][2] = ffma2(w, d2, acc[j][2]);
                    acc[j][3] = ffma2(w, d3, acc[j][3]);
                }
            }
        }
    }

    // epilogue -> NCHW
    float* ob = out + (size_t)b * COUT_MAIN * HWn + (ho << 6) + (tx << 2);
#pragma unroll
    for (int j = 0; j < 4; ++j) {
        int co0 = ty * 8 + 2 * j;
        float4 r0, r1;
        r0.x = f2lo(acc[j][0]); r0.y = f2lo(acc[j][1]);
        r0.z = f2lo(acc[j][2]); r0.w = f2lo(acc[j][3]);
        r1.x = f2hi(acc[j][0]); r1.y = f2hi(acc[j][1]);
        r1.z = f2hi(acc[j][2]); r1.w = f2hi(acc[j][3]);
        *reinterpret_cast<float4*>(ob + (size_t)co0 * HWn)       = r0;
        *reinterpret_cast<float4*>(ob + (size_t)(co0 + 1) * HWn) = r1;
    }
}

// ---------------- aux kernel: plain 3x3 conv producing offsets+masks ----------------
// Block = 2 output rows (128 px) x 32 outputs (27 used). Integer taps (pure copy
// Phase A). Ws double-buffered via cp.async.
__global__ __launch_bounds__(256, 2)
void k_aux(const float* __restrict__ b_off, const float* __restrict__ b_mod) {
    extern __shared__ float sm[];
    float* Vs  = sm;               // [128ch][128px] = 16384 floats
    float* Wsm = sm + 16384;       // [2][32*32]     =  2048 floats

    const int blk = blockIdx.x;
    const int b   = blk >> 5;
    const int ho0 = (blk & 31) << 1;
    const int t   = threadIdx.x;
    const int tx  = t & 31;        // pixel group (4 px of 128)
    const int ty  = t >> 5;        // output group (4 outs = 2 pairs)
    const int tp  = t >> 1;        // copy pixel 0..127
    const int th  = t & 1;         // copy half (64 channels)

    const uint32_t ws_sm = (uint32_t)__cvta_generic_to_shared(Wsm);

    ull acc[2][4];
#pragma unroll
    for (int j = 0; j < 2; ++j)
#pragma unroll
        for (int i = 0; i < 4; ++i) acc[j][i] = 0ULL;

    // prefetch chunk 0
    cp16(ws_sm + t * 16, (const char*)g_wt_om + t * 16);
    cp_commit();

    const float* xb = g_xnhwc + (size_t)b * HWn * CIN;

#pragma unroll 1
    for (int k = 0; k < 9; ++k) {
        const int kh = k / 3, kw = k % 3;
        __syncthreads();  // all done reading Vs from previous tap

        // Phase A: guarded row copy (integer taps)
        {
            int row = tp >> 6, col = tp & 63;
            int ys = ho0 + row + kh - 1;
            int xs = col + kw - 1;
            bool val = ((unsigned)ys < 64u) && ((unsigned)xs < 64u);
            size_t base = val ? (size_t)((ys << 6) + xs) * CIN : 0;
            const float4* s4 = reinterpret_cast<const float4*>(xb + base) + th * 16;
#pragma unroll
            for (int j = 0; j < 16; ++j) {
                float4 xv = val ? __ldg(s4 + j) : make_float4(0.f, 0.f, 0.f, 0.f);
                int c0 = (th << 6) + (j << 2);
                Vs[(c0 + 0) * 128 + tp] = xv.x;
                Vs[(c0 + 1) * 128 + tp] = xv.y;
                Vs[(c0 + 2) * 128 + tp] = xv.z;
                Vs[(c0 + 3) * 128 + tp] = xv.w;
            }
        }

#pragma unroll 1
        for (int cc = 0; cc < 4; ++cc) {
            const int g = k * 4 + cc;
            cp_wait_all();
            __syncthreads();  // Ws chunk ready; Phase A STS visible (cc==0); other buf free

            if (g + 1 < 36) {
                cp16(ws_sm + ((g + 1) & 1) * 4096 + t * 16,
                     (const char*)g_wt_om + (size_t)(g + 1) * 4096 + t * 16);
                cp_commit();
            }

            const float* wsb = Wsm + (g & 1) * 1024 + (ty << 2);
            const float* vcb = Vs + (cc << 5) * 128 + (tx << 2);
#pragma unroll 8
            for (int c = 0; c < 32; ++c) {
                float4 v4 = *reinterpret_cast<const float4*>(vcb + c * 128);
                ull d0 = dup2(v4.x), d1 = dup2(v4.y), d2 = dup2(v4.z), d3 = dup2(v4.w);
                const ull* wp = reinterpret_cast<const ull*>(wsb + c * 32);
#pragma unroll
                for (int j = 0; j < 2; ++j) {
                    ull w = wp[j];
                    acc[j][0] = ffma2(w, d0, acc[j][0]);
                    acc[j][1] = ffma2(w, d1, acc[j][1]);
                    acc[j][2] = ffma2(w, d2, acc[j][2]);
                    acc[j][3] = ffma2(w, d3, acc[j][3]);
                }
            }
        }
    }

    // epilogue: bias (+ 2*sigmoid for mask channels) -> g_offmask
#pragma unroll
    for (int j = 0; j < 2; ++j) {
#pragma unroll
        for (int h = 0; h < 2; ++h) {
            int o = (ty << 2) + (j << 1) + h;
            if (o < 27) {
                float bias = (o < 18) ? b_off[o] : b_mod[o - 18];
#pragma unroll
                for (int i = 0; i < 4; ++i) {
                    int p = (tx << 2) + i;
                    int row = ho0 + (p >> 6), col = p & 63;
                    float v = (h ? f2hi(acc[j][i]) : f2lo(acc[j][i])) + bias;
                    if (o >= 18) v = 2.f / (1.f + expf(-v));
                    g_offmask[(size_t)(((b << 6) + row) * 64 + col) * 27 + o] = v;
                }
            }
        }
    }
}

// ---------------- launch ----------------
extern "C" void kernel_launch(void* const* d_in, const int* in_sizes, int n_in,
                              void* d_out, int out_size) {
    const float* x     = (const float*)d_in[0];
    const float* w_off = (const float*)d_in[1];
    const float* b_off = (const float*)d_in[2];
    const float* w_mod = (const float*)d_in[3];
    const float* b_mod = (const float*)d_in[4];
    const float* w_reg = (const float*)d_in[5];
    float* out = (float*)d_out;

    const int SMEM_MAIN = (16384 + 8192 + 1728) * 4;   // 105216 B
    const int SMEM_AUX  = (16384 + 2048) * 4;          //  73728 B
    cudaFuncSetAttribute(k_main, cudaFuncAttributeMaxDynamicSharedMemorySize, SMEM_MAIN);
    cudaFuncSetAttribute(k_aux,  cudaFuncAttributeMaxDynamicSharedMemorySize, SMEM_AUX);

    k_transpose<<<Bn * Hn, 256>>>(x);
    k_prep<<<(9 * 128 * 128 + 9 * 128 * 32 + 255) / 256, 256>>>(w_reg, w_off, w_mod);
    k_aux<<<Bn * 32, 256, SMEM_AUX>>>(b_off, b_mod);
    k_main<<<Bn * Hn, 256, SMEM_MAIN>>>(out);
}